// round 2
// baseline (speedup 1.0000x reference)
#include <cuda_runtime.h>
#include <math.h>
#include <stdint.h>

// ---------------- problem constants ----------------
#define TPLEN 600
#define TQLEN 60
#define BATCH 64
// H=256, H2=128, EMB=344

// ---------------- scratch (device globals; no allocation allowed) ----------------
// layout (floats):
//  X0p  [600,64,384]  (re-used for X1p)
//  X0q  [60,64,384]   (re-used for X1q)
//  Hp0  [600,64,256]
//  Hq0  [60,64,256]
//  Hp1  [600,64,256]
//  Hq1  [60,64,256]
//  aq   [60,64,256]
//  ap   [600,64,256]
//  xp   [600,64,512]
//  Yq   [60,64,512]
#define N_XP   (600LL*64*384)
#define N_XQ   (60LL*64*384)
#define N_HP   (600LL*64*256)
#define N_HQ   (60LL*64*256)
#define N_XPM  (600LL*64*512)
#define N_YQ   (60LL*64*512)

#define O_X0p  0LL
#define O_X0q  (O_X0p + N_XP)
#define O_Hp0  (O_X0q + N_XQ)
#define O_Hq0  (O_Hp0 + N_HP)
#define O_Hp1  (O_Hq0 + N_HQ)
#define O_Hq1  (O_Hp1 + N_HP)
#define O_aq   (O_Hq1 + N_HQ)
#define O_ap   (O_aq  + N_HQ)
#define O_xp   (O_ap  + N_HP)
#define O_Yq   (O_xp  + N_XPM)
#define SCRATCH_TOTAL (O_Yq + N_YQ)

__device__ float g_scratch[SCRATCH_TOTAL];

// ---------------- helpers ----------------
__device__ __forceinline__ float sigf(float x) { return 1.0f / (1.0f + __expf(-x)); }
__device__ __forceinline__ float tanh_ap(float x) {
    float y;
    asm("tanh.approx.f32 %0, %1;" : "=f"(y) : "f"(x));
    return y;
}

// ---------------- GEMM: C[M,N] = A[M,K] @ W[N, wcol0:wcol0+K]^T (+ bias) ----------------
// A row-major stride K; W row-major stride ldw. M % 128 == 0, N % 128 == 0, K % 8 == 0.
__global__ __launch_bounds__(256, 2) void gemm_bias(
    const float* __restrict__ A, const float* __restrict__ W,
    const float* __restrict__ bias, float* __restrict__ C,
    int M, int N, int K, int ldw, int wcol0, int hasBias)
{
    __shared__ float As[8][132];
    __shared__ float Ws[8][132];
    int bm = blockIdx.y, bn = blockIdx.x;
    int tid = threadIdx.x;
    int tm = tid >> 4, tn = tid & 15;

    int lrow = tid >> 1;           // 0..127
    int kq   = (tid & 1) * 4;      // 0 or 4

    const float* Ag = A + (long long)(bm * 128 + lrow) * K + kq;
    const float* Wg = W + (long long)(bn * 128 + lrow) * ldw + wcol0 + kq;

    float acc[8][8];
#pragma unroll
    for (int i = 0; i < 8; i++)
#pragma unroll
        for (int j = 0; j < 8; j++) acc[i][j] = 0.0f;

    for (int k0 = 0; k0 < K; k0 += 8) {
        float4 av = *(const float4*)(Ag + k0);
        float4 wv = *(const float4*)(Wg + k0);
        __syncthreads();
        As[kq + 0][lrow] = av.x; As[kq + 1][lrow] = av.y;
        As[kq + 2][lrow] = av.z; As[kq + 3][lrow] = av.w;
        Ws[kq + 0][lrow] = wv.x; Ws[kq + 1][lrow] = wv.y;
        Ws[kq + 2][lrow] = wv.z; Ws[kq + 3][lrow] = wv.w;
        __syncthreads();
#pragma unroll
        for (int kk = 0; kk < 8; kk++) {
            float4 a0 = *(const float4*)&As[kk][tm * 8];
            float4 a1 = *(const float4*)&As[kk][tm * 8 + 4];
            float4 b0 = *(const float4*)&Ws[kk][tn * 8];
            float4 b1 = *(const float4*)&Ws[kk][tn * 8 + 4];
            float ar[8] = {a0.x, a0.y, a0.z, a0.w, a1.x, a1.y, a1.z, a1.w};
            float br[8] = {b0.x, b0.y, b0.z, b0.w, b1.x, b1.y, b1.z, b1.w};
#pragma unroll
            for (int i = 0; i < 8; i++)
#pragma unroll
                for (int j = 0; j < 8; j++) acc[i][j] += ar[i] * br[j];
        }
    }

    float bv[8];
#pragma unroll
    for (int j = 0; j < 8; j++)
        bv[j] = hasBias ? bias[bn * 128 + tn * 8 + j] : 0.0f;

#pragma unroll
    for (int i = 0; i < 8; i++) {
        long long crow = (long long)(bm * 128 + tm * 8 + i) * N + bn * 128 + tn * 8;
        float4 s0 = make_float4(acc[i][0] + bv[0], acc[i][1] + bv[1], acc[i][2] + bv[2], acc[i][3] + bv[3]);
        float4 s1 = make_float4(acc[i][4] + bv[4], acc[i][5] + bv[5], acc[i][6] + bv[6], acc[i][7] + bv[7]);
        *(float4*)(C + crow) = s0;
        *(float4*)(C + crow + 4) = s1;
    }
}

// ---------------- pre-BiLSTM scan ----------------
// Quirk: o-gate unused; h = tanh(c * mask). Gates i,f,g = Whh rows 0..383.
// X: [T, B, 384] precomputed x@Wih^T + b (rows 0..383). Hout: [T, B, 256] (fwd | bwd).
// grid = 64 (batch), block = 384. Thread j holds Whh row j in registers.
__global__ __launch_bounds__(384, 1) void pre_scan(
    const float* __restrict__ X, const float* __restrict__ mask,
    const float* __restrict__ Whh, float* __restrict__ Hout, int T)
{
    __shared__ __align__(16) float h_s[2][128];
    __shared__ __align__(16) float c_s[2][128];
    __shared__ float gates[2][384];
    int b = blockIdx.x;
    int j = threadIdx.x;

    float4 w[32];
    const float4* wrow = (const float4*)(Whh + j * 128);
#pragma unroll
    for (int i = 0; i < 32; i++) w[i] = wrow[i];

    if (j < 128) { h_s[0][j] = 0.f; h_s[1][j] = 0.f; c_s[0][j] = 0.f; c_s[1][j] = 0.f; }
    __syncthreads();

    for (int t = 0; t < T; t++) {
        int t0 = t, t1 = T - 1 - t;
        float acc0 = X[((long long)t0 * BATCH + b) * 384 + j];
        float acc1 = X[((long long)t1 * BATCH + b) * 384 + j];
        const float4* h0 = (const float4*)h_s[0];
        const float4* h1 = (const float4*)h_s[1];
#pragma unroll 8
        for (int i = 0; i < 32; i++) {
            float4 x0 = h0[i], x1 = h1[i];
            acc0 += w[i].x * x0.x + w[i].y * x0.y + w[i].z * x0.z + w[i].w * x0.w;
            acc1 += w[i].x * x1.x + w[i].y * x1.y + w[i].z * x1.z + w[i].w * x1.w;
        }
        gates[0][j] = acc0;
        gates[1][j] = acc1;
        __syncthreads();
        if (j < 256) {
            int d = j >> 7, k = j & 127;
            int td = d ? t1 : t0;
            float ig = gates[d][k], fg = gates[d][128 + k], gg = gates[d][256 + k];
            float m = mask[td * BATCH + b];
            float c2 = (sigf(fg) * c_s[d][k] + sigf(ig) * tanhf(gg)) * m;
            float h2 = tanhf(c2);
            c_s[d][k] = c2;
            h_s[d][k] = h2;
            Hout[((long long)td * BATCH + b) * 256 + d * 128 + k] = h2;
        }
        __syncthreads();
    }
}

// ---------------- Match-LSTM scan ----------------
// grid = 64 (batch), block = 512, both directions in one CTA.
// smem: Yq[60*512], aq[60*256], Wa[256], h[2*128], c[2*128], u[2*256], gates[2*512], alpha[2*64]
#define MS_YQ    0
#define MS_AQ    (MS_YQ + 60 * 512)
#define MS_WA    (MS_AQ + 60 * 256)
#define MS_H     (MS_WA + 256)
#define MS_C     (MS_H + 256)
#define MS_U     (MS_C + 256)
#define MS_G     (MS_U + 512)
#define MS_ALPHA (MS_G + 1024)
#define MS_TOTAL (MS_ALPHA + 128)
#define MATCH_SMEM_BYTES (MS_TOTAL * 4)

__global__ __launch_bounds__(512, 1) void match_scan(
    const float* __restrict__ ap,   // [600,64,256]
    const float* __restrict__ xp,   // [600,64,512]
    const float* __restrict__ aq,   // [60,64,256]
    const float* __restrict__ Yq,   // [60,64,512]
    const float* __restrict__ Wh,   // [256,128]
    const float* __restrict__ Whh,  // [512,128]
    const float* __restrict__ Wa,   // [256]
    const float* __restrict__ ba,   // [1]
    const float* __restrict__ mask, // [600,64]
    float* __restrict__ out)        // [600,64,256]
{
    extern __shared__ float sm[];
    float* Yq_s   = sm + MS_YQ;
    float* aq_s   = sm + MS_AQ;
    float* Wa_s   = sm + MS_WA;
    float* h_s    = sm + MS_H;
    float* c_sm   = sm + MS_C;
    float* u_s    = sm + MS_U;
    float* g_s    = sm + MS_G;
    float* al_s   = sm + MS_ALPHA;

    int b = blockIdx.x;
    int tid = threadIdx.x;
    int lane = tid & 31;

    for (int idx = tid; idx < 60 * 512; idx += 512) {
        int tq = idx >> 9, jj = idx & 511;
        Yq_s[idx] = Yq[((long long)tq * BATCH + b) * 512 + jj];
    }
    for (int idx = tid; idx < 60 * 256; idx += 512) {
        int tq = idx >> 8, jj = idx & 255;
        aq_s[idx] = aq[((long long)tq * BATCH + b) * 256 + jj];
    }
    if (tid < 256) Wa_s[tid] = Wa[tid];
    if (tid < 256) { h_s[tid] = 0.f; c_sm[tid] = 0.f; }
    float bav = ba[0];
    __syncthreads();

    for (int t = 0; t < TPLEN; t++) {
        int t0 = t, t1 = TPLEN - 1 - t;

        // ---- 1. u[d][i] = ap[t_d,b,i] + (h_d @ Wh^T)[i]  (pairs of threads per row)
        {
            int r = tid >> 1;
            int hh = (tid & 1) * 16;  // float4 offset: 0 or 64 floats
            const float4* wr = (const float4*)(Wh + r * 128) + hh;
            const float4* h0 = ((const float4*)h_s) + hh;
            const float4* h1 = ((const float4*)(h_s + 128)) + hh;
            float a0 = 0.f, a1 = 0.f;
#pragma unroll 8
            for (int i = 0; i < 16; i++) {
                float4 w4 = wr[i];
                float4 x0 = h0[i], x1 = h1[i];
                a0 += w4.x * x0.x + w4.y * x0.y + w4.z * x0.z + w4.w * x0.w;
                a1 += w4.x * x1.x + w4.y * x1.y + w4.z * x1.z + w4.w * x1.w;
            }
            a0 += __shfl_xor_sync(0xffffffffu, a0, 1);
            a1 += __shfl_xor_sync(0xffffffffu, a1, 1);
            if ((tid & 1) == 0) {
                u_s[r]       = ap[((long long)t0 * BATCH + b) * 256 + r] + a0;
                u_s[256 + r] = ap[((long long)t1 * BATCH + b) * 256 + r] + a1;
            }
        }
        __syncthreads();

        // ---- 2. attention logits: e[d][tq] = ba + sum_i Wa[i]*tanh(aq[tq,i] + u[d][i])
        {
            int tq = tid >> 3, l8 = tid & 7;
            if (tq < TQLEN) {
                const float* aqr = aq_s + tq * 256;
                float acc0 = 0.f, acc1 = 0.f;
#pragma unroll
                for (int ii = 0; ii < 32; ii++) {
                    int i = l8 * 32 + ((ii + lane) & 31);  // bank-stagger
                    float aval = aqr[i];
                    float wv = Wa_s[i];
                    acc0 += wv * tanh_ap(aval + u_s[i]);
                    acc1 += wv * tanh_ap(aval + u_s[256 + i]);
                }
                acc0 += __shfl_xor_sync(0xffffffffu, acc0, 1);
                acc0 += __shfl_xor_sync(0xffffffffu, acc0, 2);
                acc0 += __shfl_xor_sync(0xffffffffu, acc0, 4);
                acc1 += __shfl_xor_sync(0xffffffffu, acc1, 1);
                acc1 += __shfl_xor_sync(0xffffffffu, acc1, 2);
                acc1 += __shfl_xor_sync(0xffffffffu, acc1, 4);
                if (l8 == 0) { al_s[tq] = acc0 + bav; al_s[64 + tq] = acc1 + bav; }
            }
        }
        __syncthreads();

        // ---- 3. softmax over TQ (warp 0: fwd, warp 1: bwd)
        if (tid < 64) {
            int d = tid >> 5;
            float e0 = (lane < TQLEN) ? al_s[d * 64 + lane] : -1e30f;
            float e1 = (lane + 32 < TQLEN) ? al_s[d * 64 + lane + 32] : -1e30f;
            float mx = fmaxf(e0, e1);
#pragma unroll
            for (int o = 16; o; o >>= 1) mx = fmaxf(mx, __shfl_xor_sync(0xffffffffu, mx, o));
            float s0 = (lane < TQLEN) ? __expf(e0 - mx) : 0.f;
            float s1 = (lane + 32 < TQLEN) ? __expf(e1 - mx) : 0.f;
            float s = s0 + s1;
#pragma unroll
            for (int o = 16; o; o >>= 1) s += __shfl_xor_sync(0xffffffffu, s, o);
            float inv = 1.0f / s;
            if (lane < TQLEN) al_s[d * 64 + lane] = s0 * inv;
            if (lane + 32 < TQLEN) al_s[d * 64 + lane + 32] = s1 * inv;
        }
        __syncthreads();

        // ---- 4. gates[d][j] = xp[t_d,b,j] + (h_d @ Whh^T)[j] + sum_tq alpha[d][tq]*Yq[tq,j]
        {
            float g0 = xp[((long long)t0 * BATCH + b) * 512 + tid];
            float g1 = xp[((long long)t1 * BATCH + b) * 512 + tid];
            const float4* wr = (const float4*)(Whh + tid * 128);
            const float4* h0 = (const float4*)h_s;
            const float4* h1 = (const float4*)(h_s + 128);
#pragma unroll 8
            for (int i = 0; i < 32; i++) {
                float4 w4 = wr[i];
                float4 x0 = h0[i], x1 = h1[i];
                g0 += w4.x * x0.x + w4.y * x0.y + w4.z * x0.z + w4.w * x0.w;
                g1 += w4.x * x1.x + w4.y * x1.y + w4.z * x1.z + w4.w * x1.w;
            }
#pragma unroll 4
            for (int tq = 0; tq < TQLEN; tq++) {
                float yv = Yq_s[tq * 512 + tid];
                g0 += al_s[tq] * yv;
                g1 += al_s[64 + tq] * yv;
            }
            g_s[tid] = g0;
            g_s[512 + tid] = g1;
        }
        __syncthreads();

        // ---- 5. LSTM cell update (full cell, then h*=m, c*=m)
        if (tid < 256) {
            int d = tid >> 7, k = tid & 127;
            int td = d ? t1 : t0;
            const float* gd = g_s + d * 512;
            float ig = gd[k], fg = gd[128 + k], gg = gd[256 + k], og = gd[384 + k];
            float m = mask[td * BATCH + b];
            float c2 = sigf(fg) * c_sm[d * 128 + k] + sigf(ig) * tanhf(gg);
            float h2 = sigf(og) * tanhf(c2);
            c2 *= m; h2 *= m;
            c_sm[d * 128 + k] = c2;
            h_s[d * 128 + k] = h2;
            out[((long long)td * BATCH + b) * 256 + d * 128 + k] = h2;
        }
        __syncthreads();
    }
}

// ---------------- host ----------------
static void launch_gemm(const float* A, const float* W, const float* bias, float* C,
                        int M, int N, int K, int ldw, int wcol0)
{
    dim3 g(N / 128, M / 128);
    gemm_bias<<<g, 256>>>(A, W, bias, C, M, N, K, ldw, wcol0, bias != nullptr ? 1 : 0);
}

extern "C" void kernel_launch(void* const* d_in, const int* in_sizes, int n_in,
                              void* d_out, int out_size)
{
    const float* passage  = (const float*)d_in[0];
    const float* question = (const float*)d_in[1];
    const float* mask_p   = (const float*)d_in[2];
    const float* mask_q   = (const float*)d_in[3];
    const float* pre0_Wih = (const float*)d_in[4];
    const float* pre0_Whh = (const float*)d_in[5];
    const float* pre0_b   = (const float*)d_in[6];
    const float* pre1_Wih = (const float*)d_in[7];
    const float* pre1_Whh = (const float*)d_in[8];
    const float* pre1_b   = (const float*)d_in[9];
    const float* mq_Wq    = (const float*)d_in[10];
    const float* mq_Wp    = (const float*)d_in[11];
    const float* mq_bp    = (const float*)d_in[12];
    const float* mq_Wh    = (const float*)d_in[13];
    const float* mq_Wa    = (const float*)d_in[14];
    const float* mq_ba    = (const float*)d_in[15];
    const float* mq_Wih   = (const float*)d_in[16];
    const float* mq_Whh   = (const float*)d_in[17];
    const float* mq_b     = (const float*)d_in[18];
    float* out = (float*)d_out;

    float* s = nullptr;
    cudaGetSymbolAddress((void**)&s, g_scratch);

    float* X0p = s + O_X0p;  // also X1p
    float* X0q = s + O_X0q;  // also X1q
    float* Hp0 = s + O_Hp0;
    float* Hq0 = s + O_Hq0;
    float* Hp1 = s + O_Hp1;
    float* Hq1 = s + O_Hq1;
    float* aqb = s + O_aq;
    float* apb = s + O_ap;
    float* xpb = s + O_xp;
    float* Yqb = s + O_Yq;

    cudaFuncSetAttribute(match_scan, cudaFuncAttributeMaxDynamicSharedMemorySize,
                         MATCH_SMEM_BYTES);

    // ---- pre layer 0 (i,f,g gates only: 384 rows) ----
    launch_gemm(passage,  pre0_Wih, pre0_b, X0p, TPLEN * BATCH, 384, 344, 344, 0);
    launch_gemm(question, pre0_Wih, pre0_b, X0q, TQLEN * BATCH, 384, 344, 344, 0);
    pre_scan<<<BATCH, 384>>>(X0p, mask_p, pre0_Whh, Hp0, TPLEN);
    pre_scan<<<BATCH, 384>>>(X0q, mask_q, pre0_Whh, Hq0, TQLEN);

    // ---- pre layer 1 ----
    launch_gemm(Hp0, pre1_Wih, pre1_b, X0p, TPLEN * BATCH, 384, 256, 256, 0);
    launch_gemm(Hq0, pre1_Wih, pre1_b, X0q, TQLEN * BATCH, 384, 256, 256, 0);
    pre_scan<<<BATCH, 384>>>(X0p, mask_p, pre1_Whh, Hp1, TPLEN);
    pre_scan<<<BATCH, 384>>>(X0q, mask_q, pre1_Whh, Hq1, TQLEN);

    // ---- match precompute ----
    launch_gemm(Hq1, mq_Wq, nullptr, aqb, TQLEN * BATCH, 256, 256, 256, 0);
    launch_gemm(Hp1, mq_Wp, mq_bp,   apb, TPLEN * BATCH, 256, 256, 256, 0);
    launch_gemm(Hp1, mq_Wih, mq_b,   xpb, TPLEN * BATCH, 512, 256, 512, 0);
    launch_gemm(Hq1, mq_Wih, nullptr, Yqb, TQLEN * BATCH, 512, 256, 512, 256);

    // ---- match scan ----
    match_scan<<<BATCH, 512, MATCH_SMEM_BYTES>>>(
        apb, xpb, aqb, Yqb, mq_Wh, mq_Whh, mq_Wa, mq_ba, mask_p, out);

    (void)in_sizes; (void)n_in; (void)out_size;
}

// round 3
// speedup vs baseline: 1.0024x; 1.0024x over previous
#include <cuda_runtime.h>
#include <math.h>
#include <stdint.h>

// ---------------- problem constants ----------------
#define TPLEN 600
#define TQLEN 60
#define BATCH 64
// H=256, H2=128, EMB=344

// ---------------- scratch (device globals; no allocation allowed) ----------------
// layout (floats):
//  X0p  [600,64,384]  (re-used for X1p)
//  X0q  [60,64,384]   (re-used for X1q)
//  Hp0  [600,64,256]
//  Hq0  [60,64,256]
//  Hp1  [600,64,256]
//  Hq1  [60,64,256]
//  aq   [60,64,256]
//  ap   [600,64,256]
//  xp   [600,64,512]
//  Yq   [60,64,512]
#define N_XP   (600LL*64*384)
#define N_XQ   (60LL*64*384)
#define N_HP   (600LL*64*256)
#define N_HQ   (60LL*64*256)
#define N_XPM  (600LL*64*512)
#define N_YQ   (60LL*64*512)

#define O_X0p  0LL
#define O_X0q  (O_X0p + N_XP)
#define O_Hp0  (O_X0q + N_XQ)
#define O_Hq0  (O_Hp0 + N_HP)
#define O_Hp1  (O_Hq0 + N_HQ)
#define O_Hq1  (O_Hp1 + N_HP)
#define O_aq   (O_Hq1 + N_HQ)
#define O_ap   (O_aq  + N_HQ)
#define O_xp   (O_ap  + N_HP)
#define O_Yq   (O_xp  + N_XPM)
#define SCRATCH_TOTAL (O_Yq + N_YQ)

__device__ float g_scratch[SCRATCH_TOTAL];

// ---------------- helpers ----------------
__device__ __forceinline__ float sigf(float x) { return 1.0f / (1.0f + __expf(-x)); }
__device__ __forceinline__ float tanh_ap(float x) {
    float y;
    asm("tanh.approx.f32 %0, %1;" : "=f"(y) : "f"(x));
    return y;
}

// ---------------- GEMM: C[M,N] = A[M,K] @ W[N, wcol0:wcol0+K]^T (+ bias) ----------------
// A row-major stride K; W row-major stride ldw. M % 128 == 0, N % 128 == 0, K % 8 == 0.
__global__ __launch_bounds__(256, 2) void gemm_bias(
    const float* __restrict__ A, const float* __restrict__ W,
    const float* __restrict__ bias, float* __restrict__ C,
    int M, int N, int K, int ldw, int wcol0, int hasBias)
{
    __shared__ float As[8][132];
    __shared__ float Ws[8][132];
    int bm = blockIdx.y, bn = blockIdx.x;
    int tid = threadIdx.x;
    int tm = tid >> 4, tn = tid & 15;

    int lrow = tid >> 1;           // 0..127
    int kq   = (tid & 1) * 4;      // 0 or 4

    const float* Ag = A + (long long)(bm * 128 + lrow) * K + kq;
    const float* Wg = W + (long long)(bn * 128 + lrow) * ldw + wcol0 + kq;

    float acc[8][8];
#pragma unroll
    for (int i = 0; i < 8; i++)
#pragma unroll
        for (int j = 0; j < 8; j++) acc[i][j] = 0.0f;

    for (int k0 = 0; k0 < K; k0 += 8) {
        float4 av = *(const float4*)(Ag + k0);
        float4 wv = *(const float4*)(Wg + k0);
        __syncthreads();
        As[kq + 0][lrow] = av.x; As[kq + 1][lrow] = av.y;
        As[kq + 2][lrow] = av.z; As[kq + 3][lrow] = av.w;
        Ws[kq + 0][lrow] = wv.x; Ws[kq + 1][lrow] = wv.y;
        Ws[kq + 2][lrow] = wv.z; Ws[kq + 3][lrow] = wv.w;
        __syncthreads();
#pragma unroll
        for (int kk = 0; kk < 8; kk++) {
            float4 a0 = *(const float4*)&As[kk][tm * 8];
            float4 a1 = *(const float4*)&As[kk][tm * 8 + 4];
            float4 b0 = *(const float4*)&Ws[kk][tn * 8];
            float4 b1 = *(const float4*)&Ws[kk][tn * 8 + 4];
            float ar[8] = {a0.x, a0.y, a0.z, a0.w, a1.x, a1.y, a1.z, a1.w};
            float br[8] = {b0.x, b0.y, b0.z, b0.w, b1.x, b1.y, b1.z, b1.w};
#pragma unroll
            for (int i = 0; i < 8; i++)
#pragma unroll
                for (int j = 0; j < 8; j++) acc[i][j] += ar[i] * br[j];
        }
    }

    float bv[8];
#pragma unroll
    for (int j = 0; j < 8; j++)
        bv[j] = hasBias ? bias[bn * 128 + tn * 8 + j] : 0.0f;

#pragma unroll
    for (int i = 0; i < 8; i++) {
        long long crow = (long long)(bm * 128 + tm * 8 + i) * N + bn * 128 + tn * 8;
        float4 s0 = make_float4(acc[i][0] + bv[0], acc[i][1] + bv[1], acc[i][2] + bv[2], acc[i][3] + bv[3]);
        float4 s1 = make_float4(acc[i][4] + bv[4], acc[i][5] + bv[5], acc[i][6] + bv[6], acc[i][7] + bv[7]);
        *(float4*)(C + crow) = s0;
        *(float4*)(C + crow + 4) = s1;
    }
}

// ---------------- pre-BiLSTM scan ----------------
// Quirk: o-gate unused; h = tanh(c * mask). Gates i,f,g = Whh rows 0..383.
// X: [T, B, 384] precomputed x@Wih^T + b (rows 0..383). Hout: [T, B, 256] (fwd | bwd).
// grid = 64 (batch), block = 384. Thread j holds Whh row j in registers.
__global__ __launch_bounds__(384, 1) void pre_scan(
    const float* __restrict__ X, const float* __restrict__ mask,
    const float* __restrict__ Whh, float* __restrict__ Hout, int T)
{
    __shared__ __align__(16) float h_s[2][128];
    __shared__ __align__(16) float c_s[2][128];
    __shared__ float gates[2][384];
    int b = blockIdx.x;
    int j = threadIdx.x;

    float4 w[32];
    const float4* wrow = (const float4*)(Whh + j * 128);
#pragma unroll
    for (int i = 0; i < 32; i++) w[i] = wrow[i];

    if (j < 128) { h_s[0][j] = 0.f; h_s[1][j] = 0.f; c_s[0][j] = 0.f; c_s[1][j] = 0.f; }
    __syncthreads();

    for (int t = 0; t < T; t++) {
        int t0 = t, t1 = T - 1 - t;
        float acc0 = X[((long long)t0 * BATCH + b) * 384 + j];
        float acc1 = X[((long long)t1 * BATCH + b) * 384 + j];
        const float4* h0 = (const float4*)h_s[0];
        const float4* h1 = (const float4*)h_s[1];
#pragma unroll 8
        for (int i = 0; i < 32; i++) {
            float4 x0 = h0[i], x1 = h1[i];
            acc0 += w[i].x * x0.x + w[i].y * x0.y + w[i].z * x0.z + w[i].w * x0.w;
            acc1 += w[i].x * x1.x + w[i].y * x1.y + w[i].z * x1.z + w[i].w * x1.w;
        }
        gates[0][j] = acc0;
        gates[1][j] = acc1;
        __syncthreads();
        if (j < 256) {
            int d = j >> 7, k = j & 127;
            int td = d ? t1 : t0;
            float ig = gates[d][k], fg = gates[d][128 + k], gg = gates[d][256 + k];
            float m = mask[td * BATCH + b];
            float c2 = (sigf(fg) * c_s[d][k] + sigf(ig) * tanhf(gg)) * m;
            float h2 = tanhf(c2);
            c_s[d][k] = c2;
            h_s[d][k] = h2;
            Hout[((long long)td * BATCH + b) * 256 + d * 128 + k] = h2;
        }
        __syncthreads();
    }
}

// ---------------- Match-LSTM scan ----------------
// grid = 64 (batch), block = 512, both directions in one CTA.
// smem: Yq[60*512], aq[60*256], Wa[256], h[2*128], c[2*128], u[2*256], gates[2*512], alpha[2*64]
#define MS_YQ    0
#define MS_AQ    (MS_YQ + 60 * 512)
#define MS_WA    (MS_AQ + 60 * 256)
#define MS_H     (MS_WA + 256)
#define MS_C     (MS_H + 256)
#define MS_U     (MS_C + 256)
#define MS_G     (MS_U + 512)
#define MS_ALPHA (MS_G + 1024)
#define MS_TOTAL (MS_ALPHA + 128)
#define MATCH_SMEM_BYTES (MS_TOTAL * 4)

__global__ __launch_bounds__(512, 1) void match_scan(
    const float* __restrict__ ap,   // [600,64,256]
    const float* __restrict__ xp,   // [600,64,512]
    const float* __restrict__ aq,   // [60,64,256]
    const float* __restrict__ Yq,   // [60,64,512]
    const float* __restrict__ Wh,   // [256,128]
    const float* __restrict__ Whh,  // [512,128]
    const float* __restrict__ Wa,   // [256]
    const float* __restrict__ ba,   // [1]
    const float* __restrict__ mask, // [600,64]
    float* __restrict__ out)        // [600,64,256]
{
    extern __shared__ float sm[];
    float* Yq_s   = sm + MS_YQ;
    float* aq_s   = sm + MS_AQ;
    float* Wa_s   = sm + MS_WA;
    float* h_s    = sm + MS_H;
    float* c_sm   = sm + MS_C;
    float* u_s    = sm + MS_U;
    float* g_s    = sm + MS_G;
    float* al_s   = sm + MS_ALPHA;

    int b = blockIdx.x;
    int tid = threadIdx.x;
    int lane = tid & 31;

    for (int idx = tid; idx < 60 * 512; idx += 512) {
        int tq = idx >> 9, jj = idx & 511;
        Yq_s[idx] = Yq[((long long)tq * BATCH + b) * 512 + jj];
    }
    for (int idx = tid; idx < 60 * 256; idx += 512) {
        int tq = idx >> 8, jj = idx & 255;
        aq_s[idx] = aq[((long long)tq * BATCH + b) * 256 + jj];
    }
    if (tid < 256) Wa_s[tid] = Wa[tid];
    if (tid < 256) { h_s[tid] = 0.f; c_sm[tid] = 0.f; }
    float bav = ba[0];
    __syncthreads();

    for (int t = 0; t < TPLEN; t++) {
        int t0 = t, t1 = TPLEN - 1 - t;

        // ---- 1. u[d][i] = ap[t_d,b,i] + (h_d @ Wh^T)[i]  (pairs of threads per row)
        {
            int r = tid >> 1;
            int hh = (tid & 1) * 16;  // float4 offset: 0 or 64 floats
            const float4* wr = (const float4*)(Wh + r * 128) + hh;
            const float4* h0 = ((const float4*)h_s) + hh;
            const float4* h1 = ((const float4*)(h_s + 128)) + hh;
            float a0 = 0.f, a1 = 0.f;
#pragma unroll 8
            for (int i = 0; i < 16; i++) {
                float4 w4 = wr[i];
                float4 x0 = h0[i], x1 = h1[i];
                a0 += w4.x * x0.x + w4.y * x0.y + w4.z * x0.z + w4.w * x0.w;
                a1 += w4.x * x1.x + w4.y * x1.y + w4.z * x1.z + w4.w * x1.w;
            }
            a0 += __shfl_xor_sync(0xffffffffu, a0, 1);
            a1 += __shfl_xor_sync(0xffffffffu, a1, 1);
            if ((tid & 1) == 0) {
                u_s[r]       = ap[((long long)t0 * BATCH + b) * 256 + r] + a0;
                u_s[256 + r] = ap[((long long)t1 * BATCH + b) * 256 + r] + a1;
            }
        }
        __syncthreads();

        // ---- 2. attention logits: e[d][tq] = ba + sum_i Wa[i]*tanh(aq[tq,i] + u[d][i])
        {
            int tq = tid >> 3, l8 = tid & 7;
            if (tq < TQLEN) {
                const float* aqr = aq_s + tq * 256;
                float acc0 = 0.f, acc1 = 0.f;
#pragma unroll
                for (int ii = 0; ii < 32; ii++) {
                    int i = l8 * 32 + ((ii + lane) & 31);  // bank-stagger
                    float aval = aqr[i];
                    float wv = Wa_s[i];
                    acc0 += wv * tanh_ap(aval + u_s[i]);
                    acc1 += wv * tanh_ap(aval + u_s[256 + i]);
                }
                acc0 += __shfl_xor_sync(0xffffffffu, acc0, 1);
                acc0 += __shfl_xor_sync(0xffffffffu, acc0, 2);
                acc0 += __shfl_xor_sync(0xffffffffu, acc0, 4);
                acc1 += __shfl_xor_sync(0xffffffffu, acc1, 1);
                acc1 += __shfl_xor_sync(0xffffffffu, acc1, 2);
                acc1 += __shfl_xor_sync(0xffffffffu, acc1, 4);
                if (l8 == 0) { al_s[tq] = acc0 + bav; al_s[64 + tq] = acc1 + bav; }
            }
        }
        __syncthreads();

        // ---- 3. softmax over TQ (warp 0: fwd, warp 1: bwd)
        if (tid < 64) {
            int d = tid >> 5;
            float e0 = (lane < TQLEN) ? al_s[d * 64 + lane] : -1e30f;
            float e1 = (lane + 32 < TQLEN) ? al_s[d * 64 + lane + 32] : -1e30f;
            float mx = fmaxf(e0, e1);
#pragma unroll
            for (int o = 16; o; o >>= 1) mx = fmaxf(mx, __shfl_xor_sync(0xffffffffu, mx, o));
            float s0 = (lane < TQLEN) ? __expf(e0 - mx) : 0.f;
            float s1 = (lane + 32 < TQLEN) ? __expf(e1 - mx) : 0.f;
            float s = s0 + s1;
#pragma unroll
            for (int o = 16; o; o >>= 1) s += __shfl_xor_sync(0xffffffffu, s, o);
            float inv = 1.0f / s;
            if (lane < TQLEN) al_s[d * 64 + lane] = s0 * inv;
            if (lane + 32 < TQLEN) al_s[d * 64 + lane + 32] = s1 * inv;
        }
        __syncthreads();

        // ---- 4. gates[d][j] = xp[t_d,b,j] + (h_d @ Whh^T)[j] + sum_tq alpha[d][tq]*Yq[tq,j]
        {
            float g0 = xp[((long long)t0 * BATCH + b) * 512 + tid];
            float g1 = xp[((long long)t1 * BATCH + b) * 512 + tid];
            const float4* wr = (const float4*)(Whh + tid * 128);
            const float4* h0 = (const float4*)h_s;
            const float4* h1 = (const float4*)(h_s + 128);
#pragma unroll 8
            for (int i = 0; i < 32; i++) {
                float4 w4 = wr[i];
                float4 x0 = h0[i], x1 = h1[i];
                g0 += w4.x * x0.x + w4.y * x0.y + w4.z * x0.z + w4.w * x0.w;
                g1 += w4.x * x1.x + w4.y * x1.y + w4.z * x1.z + w4.w * x1.w;
            }
#pragma unroll 4
            for (int tq = 0; tq < TQLEN; tq++) {
                float yv = Yq_s[tq * 512 + tid];
                g0 += al_s[tq] * yv;
                g1 += al_s[64 + tq] * yv;
            }
            g_s[tid] = g0;
            g_s[512 + tid] = g1;
        }
        __syncthreads();

        // ---- 5. LSTM cell update (full cell, then h*=m, c*=m)
        if (tid < 256) {
            int d = tid >> 7, k = tid & 127;
            int td = d ? t1 : t0;
            const float* gd = g_s + d * 512;
            float ig = gd[k], fg = gd[128 + k], gg = gd[256 + k], og = gd[384 + k];
            float m = mask[td * BATCH + b];
            float c2 = sigf(fg) * c_sm[d * 128 + k] + sigf(ig) * tanhf(gg);
            float h2 = sigf(og) * tanhf(c2);
            c2 *= m; h2 *= m;
            c_sm[d * 128 + k] = c2;
            h_s[d * 128 + k] = h2;
            out[((long long)td * BATCH + b) * 256 + d * 128 + k] = h2;
        }
        __syncthreads();
    }
}

// ---------------- host ----------------
static void launch_gemm(const float* A, const float* W, const float* bias, float* C,
                        int M, int N, int K, int ldw, int wcol0)
{
    dim3 g(N / 128, M / 128);
    gemm_bias<<<g, 256>>>(A, W, bias, C, M, N, K, ldw, wcol0, bias != nullptr ? 1 : 0);
}

extern "C" void kernel_launch(void* const* d_in, const int* in_sizes, int n_in,
                              void* d_out, int out_size)
{
    const float* passage  = (const float*)d_in[0];
    const float* question = (const float*)d_in[1];
    const float* mask_p   = (const float*)d_in[2];
    const float* mask_q   = (const float*)d_in[3];
    const float* pre0_Wih = (const float*)d_in[4];
    const float* pre0_Whh = (const float*)d_in[5];
    const float* pre0_b   = (const float*)d_in[6];
    const float* pre1_Wih = (const float*)d_in[7];
    const float* pre1_Whh = (const float*)d_in[8];
    const float* pre1_b   = (const float*)d_in[9];
    const float* mq_Wq    = (const float*)d_in[10];
    const float* mq_Wp    = (const float*)d_in[11];
    const float* mq_bp    = (const float*)d_in[12];
    const float* mq_Wh    = (const float*)d_in[13];
    const float* mq_Wa    = (const float*)d_in[14];
    const float* mq_ba    = (const float*)d_in[15];
    const float* mq_Wih   = (const float*)d_in[16];
    const float* mq_Whh   = (const float*)d_in[17];
    const float* mq_b     = (const float*)d_in[18];
    float* out = (float*)d_out;

    float* s = nullptr;
    cudaGetSymbolAddress((void**)&s, g_scratch);

    float* X0p = s + O_X0p;  // also X1p
    float* X0q = s + O_X0q;  // also X1q
    float* Hp0 = s + O_Hp0;
    float* Hq0 = s + O_Hq0;
    float* Hp1 = s + O_Hp1;
    float* Hq1 = s + O_Hq1;
    float* aqb = s + O_aq;
    float* apb = s + O_ap;
    float* xpb = s + O_xp;
    float* Yqb = s + O_Yq;

    cudaFuncSetAttribute(match_scan, cudaFuncAttributeMaxDynamicSharedMemorySize,
                         MATCH_SMEM_BYTES);

    // ---- pre layer 0 (i,f,g gates only: 384 rows) ----
    launch_gemm(passage,  pre0_Wih, pre0_b, X0p, TPLEN * BATCH, 384, 344, 344, 0);
    launch_gemm(question, pre0_Wih, pre0_b, X0q, TQLEN * BATCH, 384, 344, 344, 0);
    pre_scan<<<BATCH, 384>>>(X0p, mask_p, pre0_Whh, Hp0, TPLEN);
    pre_scan<<<BATCH, 384>>>(X0q, mask_q, pre0_Whh, Hq0, TQLEN);

    // ---- pre layer 1 ----
    launch_gemm(Hp0, pre1_Wih, pre1_b, X0p, TPLEN * BATCH, 384, 256, 256, 0);
    launch_gemm(Hq0, pre1_Wih, pre1_b, X0q, TQLEN * BATCH, 384, 256, 256, 0);
    pre_scan<<<BATCH, 384>>>(X0p, mask_p, pre1_Whh, Hp1, TPLEN);
    pre_scan<<<BATCH, 384>>>(X0q, mask_q, pre1_Whh, Hq1, TQLEN);

    // ---- match precompute ----
    launch_gemm(Hq1, mq_Wq, nullptr, aqb, TQLEN * BATCH, 256, 256, 256, 0);
    launch_gemm(Hp1, mq_Wp, mq_bp,   apb, TPLEN * BATCH, 256, 256, 256, 0);
    launch_gemm(Hp1, mq_Wih, mq_b,   xpb, TPLEN * BATCH, 512, 256, 512, 0);
    launch_gemm(Hq1, mq_Wih, nullptr, Yqb, TQLEN * BATCH, 512, 256, 512, 256);

    // ---- match scan ----
    match_scan<<<BATCH, 512, MATCH_SMEM_BYTES>>>(
        apb, xpb, aqb, Yqb, mq_Wh, mq_Whh, mq_Wa, mq_ba, mask_p, out);

    (void)in_sizes; (void)n_in; (void)out_size;
}

// round 4
// speedup vs baseline: 1.8156x; 1.8112x over previous
#include <cuda_runtime.h>
#include <math.h>
#include <stdint.h>

// ---------------- problem constants ----------------
#define TPLEN 600
#define TQLEN 60
#define BATCH 64
// H=256, H2=128, EMB=344

// ---------------- scratch ----------------
#define N_XP   (600LL*64*384)
#define N_XQ   (60LL*64*384)
#define N_HP   (600LL*64*256)
#define N_HQ   (60LL*64*256)
#define N_XPM  (600LL*64*512)
#define N_YQ   (60LL*64*512)
#define N_WCAT (128LL*768)

#define O_X0p  0LL
#define O_X0q  (O_X0p + N_XP)
#define O_Hp0  (O_X0q + N_XQ)
#define O_Hq0  (O_Hp0 + N_HP)
#define O_Hp1  (O_Hq0 + N_HQ)
#define O_Hq1  (O_Hp1 + N_HP)
#define O_aq   (O_Hq1 + N_HQ)
#define O_ap   (O_aq  + N_HQ)
#define O_xp   (O_ap  + N_HP)
#define O_Yq   (O_xp  + N_XPM)
#define O_WCAT (O_Yq  + N_YQ)
#define SCRATCH_TOTAL (O_WCAT + N_WCAT)

__device__ __align__(16) float g_scratch[SCRATCH_TOTAL];

// ---------------- helpers ----------------
__device__ __forceinline__ float sigf(float x) { return 1.0f / (1.0f + __expf(-x)); }
__device__ __forceinline__ float tanh_ap(float x) {
    float y;
    asm("tanh.approx.f32 %0, %1;" : "=f"(y) : "f"(x));
    return y;
}
typedef unsigned long long ull;
__device__ __forceinline__ ull pack2(float x, float y) {
    ull r; asm("mov.b64 %0, {%1, %2};" : "=l"(r) : "f"(x), "f"(y)); return r;
}
__device__ __forceinline__ float2 unpack2(ull v) {
    float2 f; asm("mov.b64 {%0, %1}, %2;" : "=f"(f.x), "=f"(f.y) : "l"(v)); return f;
}
__device__ __forceinline__ ull fma2(ull a, ull b, ull c) {
    ull d; asm("fma.rn.f32x2 %0, %1, %2, %3;" : "=l"(d) : "l"(a), "l"(b), "l"(c)); return d;
}

// ---------------- GEMM: C[M,N] = A[M,K] @ W[N, wcol0:wcol0+K]^T (+ bias) ----------------
__global__ __launch_bounds__(256, 2) void gemm_bias(
    const float* __restrict__ A, const float* __restrict__ W,
    const float* __restrict__ bias, float* __restrict__ C,
    int M, int N, int K, int ldw, int wcol0, int hasBias)
{
    __shared__ float As[8][132];
    __shared__ float Ws[8][132];
    int bm = blockIdx.y, bn = blockIdx.x;
    int tid = threadIdx.x;
    int tm = tid >> 4, tn = tid & 15;

    int lrow = tid >> 1;
    int kq   = (tid & 1) * 4;

    const float* Ag = A + (long long)(bm * 128 + lrow) * K + kq;
    const float* Wg = W + (long long)(bn * 128 + lrow) * ldw + wcol0 + kq;

    float acc[8][8];
#pragma unroll
    for (int i = 0; i < 8; i++)
#pragma unroll
        for (int j = 0; j < 8; j++) acc[i][j] = 0.0f;

    for (int k0 = 0; k0 < K; k0 += 8) {
        float4 av = *(const float4*)(Ag + k0);
        float4 wv = *(const float4*)(Wg + k0);
        __syncthreads();
        As[kq + 0][lrow] = av.x; As[kq + 1][lrow] = av.y;
        As[kq + 2][lrow] = av.z; As[kq + 3][lrow] = av.w;
        Ws[kq + 0][lrow] = wv.x; Ws[kq + 1][lrow] = wv.y;
        Ws[kq + 2][lrow] = wv.z; Ws[kq + 3][lrow] = wv.w;
        __syncthreads();
#pragma unroll
        for (int kk = 0; kk < 8; kk++) {
            float4 a0 = *(const float4*)&As[kk][tm * 8];
            float4 a1 = *(const float4*)&As[kk][tm * 8 + 4];
            float4 b0 = *(const float4*)&Ws[kk][tn * 8];
            float4 b1 = *(const float4*)&Ws[kk][tn * 8 + 4];
            float ar[8] = {a0.x, a0.y, a0.z, a0.w, a1.x, a1.y, a1.z, a1.w};
            float br[8] = {b0.x, b0.y, b0.z, b0.w, b1.x, b1.y, b1.z, b1.w};
#pragma unroll
            for (int i = 0; i < 8; i++)
#pragma unroll
                for (int j = 0; j < 8; j++) acc[i][j] += ar[i] * br[j];
        }
    }

    float bv[8];
#pragma unroll
    for (int j = 0; j < 8; j++)
        bv[j] = hasBias ? bias[bn * 128 + tn * 8 + j] : 0.0f;

#pragma unroll
    for (int i = 0; i < 8; i++) {
        long long crow = (long long)(bm * 128 + tm * 8 + i) * N + bn * 128 + tn * 8;
        float4 s0 = make_float4(acc[i][0] + bv[0], acc[i][1] + bv[1], acc[i][2] + bv[2], acc[i][3] + bv[3]);
        float4 s1 = make_float4(acc[i][4] + bv[4], acc[i][5] + bv[5], acc[i][6] + bv[6], acc[i][7] + bv[7]);
        *(float4*)(C + crow) = s0;
        *(float4*)(C + crow + 4) = s1;
    }
}

// ---------------- weight transpose for match scan ----------------
// WcatT[k][768]: cols 0..255 = Wh^T (Wh is [256,128]), cols 256..767 = Whh^T ([512,128]).
__global__ void transpose_wcat(const float* __restrict__ Wh,
                               const float* __restrict__ Whh,
                               float* __restrict__ out)
{
    int i = blockIdx.x * 256 + threadIdx.x;   // 0 .. 128*768-1
    if (i >= 128 * 768) return;
    int k = i / 768, c = i % 768;
    out[i] = (c < 256) ? Wh[c * 128 + k] : Whh[(c - 256) * 128 + k];
}

// ---------------- pre-BiLSTM scan (unchanged) ----------------
__global__ __launch_bounds__(384, 1) void pre_scan(
    const float* __restrict__ X, const float* __restrict__ mask,
    const float* __restrict__ Whh, float* __restrict__ Hout, int T)
{
    __shared__ __align__(16) float h_s[2][128];
    __shared__ __align__(16) float c_s[2][128];
    __shared__ float gates[2][384];
    int b = blockIdx.x;
    int j = threadIdx.x;

    float4 w[32];
    const float4* wrow = (const float4*)(Whh + j * 128);
#pragma unroll
    for (int i = 0; i < 32; i++) w[i] = wrow[i];

    if (j < 128) { h_s[0][j] = 0.f; h_s[1][j] = 0.f; c_s[0][j] = 0.f; c_s[1][j] = 0.f; }
    __syncthreads();

    for (int t = 0; t < T; t++) {
        int t0 = t, t1 = T - 1 - t;
        float acc0 = X[((long long)t0 * BATCH + b) * 384 + j];
        float acc1 = X[((long long)t1 * BATCH + b) * 384 + j];
        const float4* h0 = (const float4*)h_s[0];
        const float4* h1 = (const float4*)h_s[1];
#pragma unroll 8
        for (int i = 0; i < 32; i++) {
            float4 x0 = h0[i], x1 = h1[i];
            acc0 += w[i].x * x0.x + w[i].y * x0.y + w[i].z * x0.z + w[i].w * x0.w;
            acc1 += w[i].x * x1.x + w[i].y * x1.y + w[i].z * x1.z + w[i].w * x1.w;
        }
        gates[0][j] = acc0;
        gates[1][j] = acc1;
        __syncthreads();
        if (j < 256) {
            int d = j >> 7, k = j & 127;
            int td = d ? t1 : t0;
            float ig = gates[d][k], fg = gates[d][128 + k], gg = gates[d][256 + k];
            float m = mask[td * BATCH + b];
            float c2 = (sigf(fg) * c_s[d][k] + sigf(ig) * tanhf(gg)) * m;
            float h2 = tanhf(c2);
            c_s[d][k] = c2;
            h_s[d][k] = h2;
            Hout[((long long)td * BATCH + b) * 256 + d * 128 + k] = h2;
        }
        __syncthreads();
    }
}

// ---------------- Match-LSTM scan (v2: coalesced transposed weights + f32x2) ----------------
// grid = 64 (batch), block = 512, both directions per CTA.
// smem float offsets:
#define MS_YQ    0                       // 60*512
#define MS_AQ    (MS_YQ + 60 * 512)      // 60*256
#define MS_WA    (MS_AQ + 60 * 256)      // 256
#define MS_U     (MS_WA + 256)           // 512  ([fwd 256][bwd 256])
#define MS_G     (MS_U + 512)            // 1024 ([fwd 512][bwd 512])
#define MS_HS    (MS_G + 1024)           // 512  (hsplat: [fwd 128 float2][bwd 128 float2])
#define MS_AL    (MS_HS + 512)           // 128  (scalar logits: [fwd 64][bwd 64])
#define MS_ALF2  (MS_AL + 128)           // 128  (64 ull, splatted fwd alphas)
#define MS_ALB2  (MS_ALF2 + 128)         // 128  (64 ull, splatted bwd alphas)
#define MS_TOTAL (MS_ALB2 + 128)
#define MATCH_SMEM_BYTES (MS_TOTAL * 4)

__global__ __launch_bounds__(512, 1) void match_scan(
    const float* __restrict__ ap,    // [600,64,256]
    const float* __restrict__ xp,    // [600,64,512]
    const float* __restrict__ aq,    // [60,64,256]
    const float* __restrict__ Yq,    // [60,64,512]
    const float* __restrict__ WcatT, // [128,768]
    const float* __restrict__ Wa,    // [256]
    const float* __restrict__ ba,    // [1]
    const float* __restrict__ mask,  // [600,64]
    float* __restrict__ out)         // [600,64,256]
{
    extern __shared__ __align__(16) float sm[];
    float* Yq_s  = sm + MS_YQ;
    float* aq_s  = sm + MS_AQ;
    float* Wa_s  = sm + MS_WA;
    float* u_s   = sm + MS_U;
    float* g_s   = sm + MS_G;
    float* hs_f  = sm + MS_HS;             // 128 float2 (fwd), as ull
    float* al_s  = sm + MS_AL;
    ull* alf2    = (ull*)(sm + MS_ALF2);
    ull* alb2    = (ull*)(sm + MS_ALB2);

    int b = blockIdx.x;
    int tid = threadIdx.x;
    int lane = tid & 31;

    // stage per-batch tensors to smem
    for (int idx = tid; idx < 60 * 128; idx += 512) {
        int tq = idx >> 7, jj = idx & 127;
        ((float4*)Yq_s)[idx] = *(const float4*)(Yq + ((long long)tq * BATCH + b) * 512 + jj * 4);
    }
    for (int idx = tid; idx < 60 * 64; idx += 512) {
        int tq = idx >> 6, jj = idx & 63;
        ((float4*)aq_s)[idx] = *(const float4*)(aq + ((long long)tq * BATCH + b) * 256 + jj * 4);
    }
    if (tid < 256) Wa_s[tid] = Wa[tid];
    if (tid < 512) { if (tid < 512) ((float*)(sm + MS_HS))[tid] = 0.f; }
    float bav = ba[0];
    float c_reg = 0.f;   // cell state for threads < 256 (d = tid>>7, k = tid&127)
    __syncthreads();

    const ull* hfp = (const ull*)hs_f;         // [128] fwd splats
    const ull* hbp = hfp + 128;                // [128] bwd splats

    for (int t = 0; t < TPLEN; t++) {
        int t0 = t, t1 = TPLEN - 1 - t;

        // ---- Phase A: matvec over transposed weights, both dirs packed f32x2 ----
        // thread cp<384 owns output cols {2cp, 2cp+1}; cp<128 -> u cols, else gate cols.
        ull accf = 0, accb = 0;
        if (tid < 384) {
            int cp = tid;
            float2 initf, initb;
            if (cp < 128) {
                initf = *(const float2*)(ap + ((long long)t0 * BATCH + b) * 256 + 2 * cp);
                initb = *(const float2*)(ap + ((long long)t1 * BATCH + b) * 256 + 2 * cp);
            } else {
                int gc = 2 * (cp - 128);
                initf = *(const float2*)(xp + ((long long)t0 * BATCH + b) * 512 + gc);
                initb = *(const float2*)(xp + ((long long)t1 * BATCH + b) * 512 + gc);
            }
            accf = pack2(initf.x, initf.y);
            accb = pack2(initb.x, initb.y);
            const ull* wp = (const ull*)WcatT + cp;
#pragma unroll 8
            for (int k = 0; k < 128; k++) {
                ull w2 = wp[k * 384];
                accf = fma2(w2, hfp[k], accf);
                accb = fma2(w2, hbp[k], accb);
            }
            if (cp < 128) {
                float2 f = unpack2(accf), bb2 = unpack2(accb);
                *(float2*)&u_s[2 * cp]       = f;
                *(float2*)&u_s[256 + 2 * cp] = bb2;
            }
        }
        __syncthreads();

        // ---- Phase 2: attention logits e[d][tq] = ba + sum_i Wa[i]*tanh(aq[tq,i]+u[d][i])
        {
            int tq = tid >> 3, l8 = tid & 7;
            if (tq < TQLEN) {
                const float* aqr = aq_s + tq * 256;
                float a0 = 0.f, a1 = 0.f;
#pragma unroll
                for (int ii = 0; ii < 32; ii++) {
                    int i = l8 * 32 + ((ii + lane) & 31);  // bank-stagger
                    float aval = aqr[i];
                    float wv = Wa_s[i];
                    a0 += wv * tanh_ap(aval + u_s[i]);
                    a1 += wv * tanh_ap(aval + u_s[256 + i]);
                }
                a0 += __shfl_xor_sync(0xffffffffu, a0, 1);
                a0 += __shfl_xor_sync(0xffffffffu, a0, 2);
                a0 += __shfl_xor_sync(0xffffffffu, a0, 4);
                a1 += __shfl_xor_sync(0xffffffffu, a1, 1);
                a1 += __shfl_xor_sync(0xffffffffu, a1, 2);
                a1 += __shfl_xor_sync(0xffffffffu, a1, 4);
                if (l8 == 0) { al_s[tq] = a0 + bav; al_s[64 + tq] = a1 + bav; }
            }
        }
        __syncthreads();

        // ---- Phase 3: softmax over TQ; write splatted alphas
        if (tid < 64) {
            int d = tid >> 5;
            float e0 = (lane < TQLEN) ? al_s[d * 64 + lane] : -1e30f;
            float e1 = (lane + 32 < TQLEN) ? al_s[d * 64 + lane + 32] : -1e30f;
            float mx = fmaxf(e0, e1);
#pragma unroll
            for (int o = 16; o; o >>= 1) mx = fmaxf(mx, __shfl_xor_sync(0xffffffffu, mx, o));
            float s0 = (lane < TQLEN) ? __expf(e0 - mx) : 0.f;
            float s1 = (lane + 32 < TQLEN) ? __expf(e1 - mx) : 0.f;
            float s = s0 + s1;
#pragma unroll
            for (int o = 16; o; o >>= 1) s += __shfl_xor_sync(0xffffffffu, s, o);
            float inv = 1.0f / s;
            ull* dst = d ? alb2 : alf2;
            if (lane < TQLEN) { float v = s0 * inv; dst[lane] = pack2(v, v); }
            if (lane + 32 < TQLEN) { float v = s1 * inv; dst[lane + 32] = pack2(v, v); }
        }
        __syncthreads();

        // ---- Phase 4: gates += sum_tq alpha[d][tq] * Yq[tq]; store to g_s
        if (tid >= 128 && tid < 384) {
            int gp = tid - 128;  // gate pair 0..255 (cols 2gp, 2gp+1)
            const ull* yq2 = (const ull*)Yq_s + gp;
#pragma unroll 4
            for (int tq = 0; tq < TQLEN; tq++) {
                ull y = yq2[tq * 256];
                accf = fma2(alf2[tq], y, accf);
                accb = fma2(alb2[tq], y, accb);
            }
            float2 f = unpack2(accf), bb2 = unpack2(accb);
            *(float2*)&g_s[2 * gp]       = f;
            *(float2*)&g_s[512 + 2 * gp] = bb2;
        }
        __syncthreads();

        // ---- Phase 5: LSTM cell (c in registers), write h splats + output
        if (tid < 256) {
            int d = tid >> 7, k = tid & 127;
            int td = d ? t1 : t0;
            const float* gd = g_s + d * 512;
            float ig = gd[k], fg = gd[128 + k], gg = gd[256 + k], og = gd[384 + k];
            float m = mask[td * BATCH + b];
            float c2 = sigf(fg) * c_reg + sigf(ig) * tanhf(gg);
            float h2 = sigf(og) * tanhf(c2);
            c2 *= m; h2 *= m;
            c_reg = c2;
            ((ull*)hs_f)[d * 128 + k] = pack2(h2, h2);
            out[((long long)td * BATCH + b) * 256 + d * 128 + k] = h2;
        }
        __syncthreads();
    }
}

// ---------------- host ----------------
static void launch_gemm(const float* A, const float* W, const float* bias, float* C,
                        int M, int N, int K, int ldw, int wcol0)
{
    dim3 g(N / 128, M / 128);
    gemm_bias<<<g, 256>>>(A, W, bias, C, M, N, K, ldw, wcol0, bias != nullptr ? 1 : 0);
}

extern "C" void kernel_launch(void* const* d_in, const int* in_sizes, int n_in,
                              void* d_out, int out_size)
{
    const float* passage  = (const float*)d_in[0];
    const float* question = (const float*)d_in[1];
    const float* mask_p   = (const float*)d_in[2];
    const float* mask_q   = (const float*)d_in[3];
    const float* pre0_Wih = (const float*)d_in[4];
    const float* pre0_Whh = (const float*)d_in[5];
    const float* pre0_b   = (const float*)d_in[6];
    const float* pre1_Wih = (const float*)d_in[7];
    const float* pre1_Whh = (const float*)d_in[8];
    const float* pre1_b   = (const float*)d_in[9];
    const float* mq_Wq    = (const float*)d_in[10];
    const float* mq_Wp    = (const float*)d_in[11];
    const float* mq_bp    = (const float*)d_in[12];
    const float* mq_Wh    = (const float*)d_in[13];
    const float* mq_Wa    = (const float*)d_in[14];
    const float* mq_ba    = (const float*)d_in[15];
    const float* mq_Wih   = (const float*)d_in[16];
    const float* mq_Whh   = (const float*)d_in[17];
    const float* mq_b     = (const float*)d_in[18];
    float* out = (float*)d_out;

    float* s = nullptr;
    cudaGetSymbolAddress((void**)&s, g_scratch);

    float* X0p = s + O_X0p;
    float* X0q = s + O_X0q;
    float* Hp0 = s + O_Hp0;
    float* Hq0 = s + O_Hq0;
    float* Hp1 = s + O_Hp1;
    float* Hq1 = s + O_Hq1;
    float* aqb = s + O_aq;
    float* apb = s + O_ap;
    float* xpb = s + O_xp;
    float* Yqb = s + O_Yq;
    float* WcatT = s + O_WCAT;

    cudaFuncSetAttribute(match_scan, cudaFuncAttributeMaxDynamicSharedMemorySize,
                         MATCH_SMEM_BYTES);

    // weight transpose for the match scan (independent of data path)
    transpose_wcat<<<(128 * 768 + 255) / 256, 256>>>(mq_Wh, mq_Whh, WcatT);

    // ---- pre layer 0 (i,f,g gates only: 384 rows) ----
    launch_gemm(passage,  pre0_Wih, pre0_b, X0p, TPLEN * BATCH, 384, 344, 344, 0);
    launch_gemm(question, pre0_Wih, pre0_b, X0q, TQLEN * BATCH, 384, 344, 344, 0);
    pre_scan<<<BATCH, 384>>>(X0p, mask_p, pre0_Whh, Hp0, TPLEN);
    pre_scan<<<BATCH, 384>>>(X0q, mask_q, pre0_Whh, Hq0, TQLEN);

    // ---- pre layer 1 ----
    launch_gemm(Hp0, pre1_Wih, pre1_b, X0p, TPLEN * BATCH, 384, 256, 256, 0);
    launch_gemm(Hq0, pre1_Wih, pre1_b, X0q, TQLEN * BATCH, 384, 256, 256, 0);
    pre_scan<<<BATCH, 384>>>(X0p, mask_p, pre1_Whh, Hp1, TPLEN);
    pre_scan<<<BATCH, 384>>>(X0q, mask_q, pre1_Whh, Hq1, TQLEN);

    // ---- match precompute ----
    launch_gemm(Hq1, mq_Wq, nullptr, aqb, TQLEN * BATCH, 256, 256, 256, 0);
    launch_gemm(Hp1, mq_Wp, mq_bp,   apb, TPLEN * BATCH, 256, 256, 256, 0);
    launch_gemm(Hp1, mq_Wih, mq_b,   xpb, TPLEN * BATCH, 512, 256, 512, 0);
    launch_gemm(Hq1, mq_Wih, nullptr, Yqb, TQLEN * BATCH, 512, 256, 512, 256);

    // ---- match scan ----
    match_scan<<<BATCH, 512, MATCH_SMEM_BYTES>>>(
        apb, xpb, aqb, Yqb, WcatT, mq_Wa, mq_ba, mask_p, out);

    (void)in_sizes; (void)n_in; (void)out_size;
}

// round 5
// speedup vs baseline: 2.0641x; 1.1369x over previous
#include <cuda_runtime.h>
#include <cuda_bf16.h>
#include <math.h>
#include <stdint.h>

// ---------------- problem constants ----------------
#define TPLEN 600
#define TQLEN 60
#define BATCH 64
// H=256, H2=128, EMB=344

// ---------------- scratch ----------------
#define N_XP   (600LL*64*384)
#define N_XQ   (60LL*64*384)
#define N_HP   (600LL*64*256)
#define N_HQ   (60LL*64*256)
#define N_XPM  (600LL*64*512)
#define N_YQ   (60LL*64*512)
#define N_WCATB (128LL*384)          // u32 elements (bf16 pairs), stored as float slots

#define O_X0p  0LL
#define O_X0q  (O_X0p + N_XP)
#define O_Hp0  (O_X0q + N_XQ)
#define O_Hq0  (O_Hp0 + N_HP)
#define O_Hp1  (O_Hq0 + N_HQ)
#define O_Hq1  (O_Hp1 + N_HP)
#define O_aq   (O_Hq1 + N_HQ)
#define O_ap   (O_aq  + N_HQ)
#define O_xp   (O_ap  + N_HP)
#define O_Yq   (O_xp  + N_XPM)
#define O_WCB  (O_Yq  + N_YQ)
#define SCRATCH_TOTAL (O_WCB + N_WCATB)

__device__ __align__(16) float g_scratch[SCRATCH_TOTAL];

// ---------------- helpers ----------------
__device__ __forceinline__ float sigf(float x) { return 1.0f / (1.0f + __expf(-x)); }
__device__ __forceinline__ float tanh_ap(float x) {
    float y;
    asm("tanh.approx.f32 %0, %1;" : "=f"(y) : "f"(x));
    return y;
}
typedef unsigned long long ull;
__device__ __forceinline__ ull pack2(float x, float y) {
    ull r; asm("mov.b64 %0, {%1, %2};" : "=l"(r) : "f"(x), "f"(y)); return r;
}
__device__ __forceinline__ float2 unpack2(ull v) {
    float2 f; asm("mov.b64 {%0, %1}, %2;" : "=f"(f.x), "=f"(f.y) : "l"(v)); return f;
}
__device__ __forceinline__ ull fma2(ull a, ull b, ull c) {
    ull d; asm("fma.rn.f32x2 %0, %1, %2, %3;" : "=l"(d) : "l"(a), "l"(b), "l"(c)); return d;
}

// ---------------- GEMM: C[M,N] = A[M,K] @ W[N, wcol0:wcol0+K]^T (+ bias) ----------------
__global__ __launch_bounds__(256, 2) void gemm_bias(
    const float* __restrict__ A, const float* __restrict__ W,
    const float* __restrict__ bias, float* __restrict__ C,
    int M, int N, int K, int ldw, int wcol0, int hasBias)
{
    __shared__ float As[8][132];
    __shared__ float Ws[8][132];
    int bm = blockIdx.y, bn = blockIdx.x;
    int tid = threadIdx.x;
    int tm = tid >> 4, tn = tid & 15;

    int lrow = tid >> 1;
    int kq   = (tid & 1) * 4;

    const float* Ag = A + (long long)(bm * 128 + lrow) * K + kq;
    const float* Wg = W + (long long)(bn * 128 + lrow) * ldw + wcol0 + kq;

    float acc[8][8];
#pragma unroll
    for (int i = 0; i < 8; i++)
#pragma unroll
        for (int j = 0; j < 8; j++) acc[i][j] = 0.0f;

    for (int k0 = 0; k0 < K; k0 += 8) {
        float4 av = *(const float4*)(Ag + k0);
        float4 wv = *(const float4*)(Wg + k0);
        __syncthreads();
        As[kq + 0][lrow] = av.x; As[kq + 1][lrow] = av.y;
        As[kq + 2][lrow] = av.z; As[kq + 3][lrow] = av.w;
        Ws[kq + 0][lrow] = wv.x; Ws[kq + 1][lrow] = wv.y;
        Ws[kq + 2][lrow] = wv.z; Ws[kq + 3][lrow] = wv.w;
        __syncthreads();
#pragma unroll
        for (int kk = 0; kk < 8; kk++) {
            float4 a0 = *(const float4*)&As[kk][tm * 8];
            float4 a1 = *(const float4*)&As[kk][tm * 8 + 4];
            float4 b0 = *(const float4*)&Ws[kk][tn * 8];
            float4 b1 = *(const float4*)&Ws[kk][tn * 8 + 4];
            float ar[8] = {a0.x, a0.y, a0.z, a0.w, a1.x, a1.y, a1.z, a1.w};
            float br[8] = {b0.x, b0.y, b0.z, b0.w, b1.x, b1.y, b1.z, b1.w};
#pragma unroll
            for (int i = 0; i < 8; i++)
#pragma unroll
                for (int j = 0; j < 8; j++) acc[i][j] += ar[i] * br[j];
        }
    }

    float bv[8];
#pragma unroll
    for (int j = 0; j < 8; j++)
        bv[j] = hasBias ? bias[bn * 128 + tn * 8 + j] : 0.0f;

#pragma unroll
    for (int i = 0; i < 8; i++) {
        long long crow = (long long)(bm * 128 + tm * 8 + i) * N + bn * 128 + tn * 8;
        float4 s0 = make_float4(acc[i][0] + bv[0], acc[i][1] + bv[1], acc[i][2] + bv[2], acc[i][3] + bv[3]);
        float4 s1 = make_float4(acc[i][4] + bv[4], acc[i][5] + bv[5], acc[i][6] + bv[6], acc[i][7] + bv[7]);
        *(float4*)(C + crow) = s0;
        *(float4*)(C + crow + 4) = s1;
    }
}

// ---------------- weight pack for match scan ----------------
// WcatB[k][384] u32; bits[15:0]=bf16 of W(2c,k), bits[31:16]=bf16 of W(2c+1,k).
// W(col,k): col<256 -> Wh[col*128+k] (Wh [256,128]); else Whh[(col-256)*128+k] ([512,128]).
__global__ void make_wcatb(const float* __restrict__ Wh,
                           const float* __restrict__ Whh,
                           unsigned* __restrict__ out)
{
    int i = blockIdx.x * 256 + threadIdx.x;   // 0 .. 128*384-1
    if (i >= 128 * 384) return;
    int k = i / 384, c = i % 384;
    int c0 = 2 * c, c1 = 2 * c + 1;
    float w0 = (c0 < 256) ? Wh[c0 * 128 + k] : Whh[(c0 - 256) * 128 + k];
    float w1 = (c1 < 256) ? Wh[c1 * 128 + k] : Whh[(c1 - 256) * 128 + k];
    unsigned lo = (unsigned)__bfloat16_as_ushort(__float2bfloat16(w0));
    unsigned hi = (unsigned)__bfloat16_as_ushort(__float2bfloat16(w1));
    out[i] = lo | (hi << 16);
}

// ---------------- pre-BiLSTM scan (one direction per CTA) ----------------
// grid = 128 (b = bx&63, d = bx>>6), block = 384.
__global__ __launch_bounds__(384, 1) void pre_scan(
    const float* __restrict__ X, const float* __restrict__ mask,
    const float* __restrict__ Whh, float* __restrict__ Hout, int T)
{
    __shared__ __align__(16) float h_s[128];
    __shared__ __align__(16) float c_s[128];
    __shared__ float gates[384];
    int b = blockIdx.x & 63;
    int d = blockIdx.x >> 6;
    int j = threadIdx.x;

    float4 w[32];
    const float4* wrow = (const float4*)(Whh + j * 128);
#pragma unroll
    for (int i = 0; i < 32; i++) w[i] = wrow[i];

    if (j < 128) { h_s[j] = 0.f; c_s[j] = 0.f; }
    __syncthreads();

    for (int t = 0; t < T; t++) {
        int td = d ? (T - 1 - t) : t;
        float acc = X[((long long)td * BATCH + b) * 384 + j];
        const float4* h0 = (const float4*)h_s;
#pragma unroll 8
        for (int i = 0; i < 32; i++) {
            float4 x0 = h0[i];
            acc += w[i].x * x0.x + w[i].y * x0.y + w[i].z * x0.z + w[i].w * x0.w;
        }
        gates[j] = acc;
        __syncthreads();
        if (j < 128) {
            float ig = gates[j], fg = gates[128 + j], gg = gates[256 + j];
            float m = mask[td * BATCH + b];
            float c2 = (sigf(fg) * c_s[j] + sigf(ig) * tanhf(gg)) * m;
            float h2 = tanhf(c2);
            c_s[j] = c2;
            h_s[j] = h2;
            Hout[((long long)td * BATCH + b) * 256 + d * 128 + j] = h2;
        }
        __syncthreads();
    }
}

// ---------------- Match-LSTM scan (v3: one direction per CTA, bf16 weights) ----------------
// grid = 128 (b = bx&63, d = bx>>6), block = 512.
// smem float offsets:
#define MS_YQ    0                       // 60*512
#define MS_AQ    (MS_YQ + 60 * 512)      // 60*256
#define MS_WA    (MS_AQ + 60 * 256)      // 256
#define MS_U     (MS_WA + 256)           // 256
#define MS_G     (MS_U + 256)            // 512
#define MS_HS    (MS_G + 512)            // 256  (128 ull h-splats)
#define MS_AL    (MS_HS + 256)           // 64   (scalar logits)
#define MS_AL2   (MS_AL + 64)            // 128  (64 ull splatted alphas)
#define MS_TOTAL (MS_AL2 + 128)
#define MATCH_SMEM_BYTES (MS_TOTAL * 4)

__global__ __launch_bounds__(512, 1) void match_scan(
    const float* __restrict__ ap,       // [600,64,256]
    const float* __restrict__ xp,       // [600,64,512]
    const float* __restrict__ aq,       // [60,64,256]
    const float* __restrict__ Yq,       // [60,64,512]
    const unsigned* __restrict__ WcatB, // [128,384] packed bf16 col-pairs
    const float* __restrict__ Wa,       // [256]
    const float* __restrict__ ba,       // [1]
    const float* __restrict__ mask,     // [600,64]
    float* __restrict__ out)            // [600,64,256]
{
    extern __shared__ __align__(16) float sm[];
    float* Yq_s = sm + MS_YQ;
    float* aq_s = sm + MS_AQ;
    float* Wa_s = sm + MS_WA;
    float* u_s  = sm + MS_U;
    float* g_s  = sm + MS_G;
    ull*   hsp  = (ull*)(sm + MS_HS);
    float* al_s = sm + MS_AL;
    ull*   al2  = (ull*)(sm + MS_AL2);

    int b = blockIdx.x & 63;
    int d = blockIdx.x >> 6;
    int tid = threadIdx.x;
    int lane = tid & 31;

    // stage per-batch tensors to smem
    for (int idx = tid; idx < 60 * 128; idx += 512) {
        int tq = idx >> 7, jj = idx & 127;
        ((float4*)Yq_s)[idx] = *(const float4*)(Yq + ((long long)tq * BATCH + b) * 512 + jj * 4);
    }
    for (int idx = tid; idx < 60 * 64; idx += 512) {
        int tq = idx >> 6, jj = idx & 63;
        ((float4*)aq_s)[idx] = *(const float4*)(aq + ((long long)tq * BATCH + b) * 256 + jj * 4);
    }
    if (tid < 256) Wa_s[tid] = Wa[tid];
    if (tid < 128) hsp[tid] = 0ull;
    float bav = ba[0];
    float c_reg = 0.f;   // cell state for tid<128 (unit k = tid)
    __syncthreads();

    for (int t = 0; t < TPLEN; t++) {
        int td = d ? (TPLEN - 1 - t) : t;

        // ---- Phase A: [u | gates](768 cols) = init + h @ Wcat, col pairs, bf16 weights
        ull acc = 0;
        if (tid < 384) {
            int cp = tid;
            float2 init;
            if (cp < 128)
                init = *(const float2*)(ap + ((long long)td * BATCH + b) * 256 + 2 * cp);
            else
                init = *(const float2*)(xp + ((long long)td * BATCH + b) * 512 + 2 * (cp - 128));
            acc = pack2(init.x, init.y);
            const unsigned* wp = WcatB + cp;
#pragma unroll 8
            for (int k = 0; k < 128; k++) {
                unsigned v = wp[k * 384];
                ull w2 = pack2(__uint_as_float(v << 16),
                               __uint_as_float(v & 0xFFFF0000u));
                acc = fma2(w2, hsp[k], acc);
            }
            if (cp < 128) {
                float2 f = unpack2(acc);
                *(float2*)&u_s[2 * cp] = f;
            }
        }
        __syncthreads();

        // ---- Phase 2: logits e[tq] = ba + sum_i Wa[i]*tanh(aq[tq,i] + u[i])
        {
            int tq = tid >> 3, l8 = tid & 7;
            if (tq < TQLEN) {
                const float* aqr = aq_s + tq * 256;
                float a0 = 0.f;
#pragma unroll
                for (int ii = 0; ii < 32; ii++) {
                    int i = l8 * 32 + ((ii + lane) & 31);  // bank-stagger
                    a0 += Wa_s[i] * tanh_ap(aqr[i] + u_s[i]);
                }
                a0 += __shfl_xor_sync(0xffffffffu, a0, 1);
                a0 += __shfl_xor_sync(0xffffffffu, a0, 2);
                a0 += __shfl_xor_sync(0xffffffffu, a0, 4);
                if (l8 == 0) al_s[tq] = a0 + bav;
            }
        }
        __syncthreads();

        // ---- Phase 3: softmax over TQ (warp 0), write splatted alphas
        if (tid < 32) {
            float e0 = (lane < TQLEN) ? al_s[lane] : -1e30f;
            float e1 = (lane + 32 < TQLEN) ? al_s[lane + 32] : -1e30f;
            float mx = fmaxf(e0, e1);
#pragma unroll
            for (int o = 16; o; o >>= 1) mx = fmaxf(mx, __shfl_xor_sync(0xffffffffu, mx, o));
            float s0 = (lane < TQLEN) ? __expf(e0 - mx) : 0.f;
            float s1 = (lane + 32 < TQLEN) ? __expf(e1 - mx) : 0.f;
            float s = s0 + s1;
#pragma unroll
            for (int o = 16; o; o >>= 1) s += __shfl_xor_sync(0xffffffffu, s, o);
            float inv = 1.0f / s;
            if (lane < TQLEN) { float v = s0 * inv; al2[lane] = pack2(v, v); }
            if (lane + 32 < TQLEN) { float v = s1 * inv; al2[lane + 32] = pack2(v, v); }
        }
        __syncthreads();

        // ---- Phase 4: gates += sum_tq alpha[tq] * Yq[tq]; store to g_s
        if (tid >= 128 && tid < 384) {
            int gp = tid - 128;  // gate col pair (2gp, 2gp+1)
            const ull* yq2 = (const ull*)Yq_s + gp;
#pragma unroll 4
            for (int tq = 0; tq < TQLEN; tq++) {
                acc = fma2(al2[tq], yq2[tq * 256], acc);
            }
            float2 f = unpack2(acc);
            *(float2*)&g_s[2 * gp] = f;
        }
        __syncthreads();

        // ---- Phase 5: LSTM cell (c in registers), write h splats + output
        if (tid < 128) {
            int k = tid;
            float ig = g_s[k], fg = g_s[128 + k], gg = g_s[256 + k], og = g_s[384 + k];
            float m = mask[td * BATCH + b];
            float c2 = sigf(fg) * c_reg + sigf(ig) * tanhf(gg);
            float h2 = sigf(og) * tanhf(c2);
            c2 *= m; h2 *= m;
            c_reg = c2;
            hsp[k] = pack2(h2, h2);
            out[((long long)td * BATCH + b) * 256 + d * 128 + k] = h2;
        }
        __syncthreads();
    }
}

// ---------------- host ----------------
static void launch_gemm(const float* A, const float* W, const float* bias, float* C,
                        int M, int N, int K, int ldw, int wcol0)
{
    dim3 g(N / 128, M / 128);
    gemm_bias<<<g, 256>>>(A, W, bias, C, M, N, K, ldw, wcol0, bias != nullptr ? 1 : 0);
}

extern "C" void kernel_launch(void* const* d_in, const int* in_sizes, int n_in,
                              void* d_out, int out_size)
{
    const float* passage  = (const float*)d_in[0];
    const float* question = (const float*)d_in[1];
    const float* mask_p   = (const float*)d_in[2];
    const float* mask_q   = (const float*)d_in[3];
    const float* pre0_Wih = (const float*)d_in[4];
    const float* pre0_Whh = (const float*)d_in[5];
    const float* pre0_b   = (const float*)d_in[6];
    const float* pre1_Wih = (const float*)d_in[7];
    const float* pre1_Whh = (const float*)d_in[8];
    const float* pre1_b   = (const float*)d_in[9];
    const float* mq_Wq    = (const float*)d_in[10];
    const float* mq_Wp    = (const float*)d_in[11];
    const float* mq_bp    = (const float*)d_in[12];
    const float* mq_Wh    = (const float*)d_in[13];
    const float* mq_Wa    = (const float*)d_in[14];
    const float* mq_ba    = (const float*)d_in[15];
    const float* mq_Wih   = (const float*)d_in[16];
    const float* mq_Whh   = (const float*)d_in[17];
    const float* mq_b     = (const float*)d_in[18];
    float* out = (float*)d_out;

    float* s = nullptr;
    cudaGetSymbolAddress((void**)&s, g_scratch);

    float* X0p = s + O_X0p;
    float* X0q = s + O_X0q;
    float* Hp0 = s + O_Hp0;
    float* Hq0 = s + O_Hq0;
    float* Hp1 = s + O_Hp1;
    float* Hq1 = s + O_Hq1;
    float* aqb = s + O_aq;
    float* apb = s + O_ap;
    float* xpb = s + O_xp;
    float* Yqb = s + O_Yq;
    unsigned* WcatB = (unsigned*)(s + O_WCB);

    cudaFuncSetAttribute(match_scan, cudaFuncAttributeMaxDynamicSharedMemorySize,
                         MATCH_SMEM_BYTES);

    // bf16 weight pack for the match scan (independent of data path)
    make_wcatb<<<(128 * 384 + 255) / 256, 256>>>(mq_Wh, mq_Whh, WcatB);

    // ---- pre layer 0 (i,f,g gates only: 384 rows) ----
    launch_gemm(passage,  pre0_Wih, pre0_b, X0p, TPLEN * BATCH, 384, 344, 344, 0);
    launch_gemm(question, pre0_Wih, pre0_b, X0q, TQLEN * BATCH, 384, 344, 344, 0);
    pre_scan<<<2 * BATCH, 384>>>(X0p, mask_p, pre0_Whh, Hp0, TPLEN);
    pre_scan<<<2 * BATCH, 384>>>(X0q, mask_q, pre0_Whh, Hq0, TQLEN);

    // ---- pre layer 1 ----
    launch_gemm(Hp0, pre1_Wih, pre1_b, X0p, TPLEN * BATCH, 384, 256, 256, 0);
    launch_gemm(Hq0, pre1_Wih, pre1_b, X0q, TQLEN * BATCH, 384, 256, 256, 0);
    pre_scan<<<2 * BATCH, 384>>>(X0p, mask_p, pre1_Whh, Hp1, TPLEN);
    pre_scan<<<2 * BATCH, 384>>>(X0q, mask_q, pre1_Whh, Hq1, TQLEN);

    // ---- match precompute ----
    launch_gemm(Hq1, mq_Wq, nullptr, aqb, TQLEN * BATCH, 256, 256, 256, 0);
    launch_gemm(Hp1, mq_Wp, mq_bp,   apb, TPLEN * BATCH, 256, 256, 256, 0);
    launch_gemm(Hp1, mq_Wih, mq_b,   xpb, TPLEN * BATCH, 512, 256, 512, 0);
    launch_gemm(Hq1, mq_Wih, nullptr, Yqb, TQLEN * BATCH, 512, 256, 512, 256);

    // ---- match scan ----
    match_scan<<<2 * BATCH, 512, MATCH_SMEM_BYTES>>>(
        apb, xpb, aqb, Yqb, WcatB, mq_Wa, mq_ba, mask_p, out);

    (void)in_sizes; (void)n_in; (void)out_size;
}